// round 11
// baseline (speedup 1.0000x reference)
#include <cuda_runtime.h>
#include <cuda_bf16.h>
#include <cstdint>
#include <cstddef>

#define B 256
#define L 2048
#define H 128
#define V 32000
#define BL (B * L)
#define TOK 128

typedef unsigned long long u64;
typedef uint32_t u32;

// ---------------------------------------------------------------------------
// helpers
// ---------------------------------------------------------------------------
__device__ __forceinline__ u32 smem_u32(const void* p) {
    return (u32)__cvta_generic_to_shared(p);
}

__device__ __forceinline__ void ldsm_x4(u32* r, u32 addr) {
    asm volatile("ldmatrix.sync.aligned.m8n8.x4.shared.b16 {%0,%1,%2,%3}, [%4];"
                 : "=r"(r[0]), "=r"(r[1]), "=r"(r[2]), "=r"(r[3]) : "r"(addr));
}

__device__ __forceinline__ void mma16816(float* d, const u32* a, u32 b0, u32 b1) {
    asm volatile(
        "mma.sync.aligned.m16n8k16.row.col.f32.bf16.bf16.f32 "
        "{%0,%1,%2,%3}, {%4,%5,%6,%7}, {%8,%9}, {%0,%1,%2,%3};"
        : "+f"(d[0]), "+f"(d[1]), "+f"(d[2]), "+f"(d[3])
        : "r"(a[0]), "r"(a[1]), "r"(a[2]), "r"(a[3]), "r"(b0), "r"(b1));
}

__device__ __forceinline__ void cp16(u32 dst, const void* src) {
    asm volatile("cp.async.cg.shared.global [%0], [%1], 16;" :: "r"(dst), "l"(src));
}

// Packed dual-FMA (scan/out kernels).
__device__ __forceinline__ float2 ffma2(float2 a, float2 b, float2 c) {
    float2 d;
    asm("fma.rn.f32x2 %0, %1, %2, %3;"
        : "=l"(*(u64*)&d)
        : "l"(*(u64*)&a), "l"(*(u64*)&b), "l"(*(u64*)&c));
    return d;
}

// 3-way bf16 split: x = a0+a1+a2 + O(2^-27 * x)
__device__ __forceinline__ void split3(float x, __nv_bfloat16* a) {
    a[0] = __float2bfloat16(x);
    float r = x - __bfloat162float(a[0]);
    a[1] = __float2bfloat16(r);  r -= __bfloat162float(a[1]);
    a[2] = __float2bfloat16(r);
}
__device__ __forceinline__ u32 pack_bf2(__nv_bfloat16 lo, __nv_bfloat16 hi) {
    __nv_bfloat162 p;
    p.x = lo; p.y = hi;
    return *(u32*)&p;
}

// XOR chunk swizzles: conflict-free ldmatrix on natural row strides.
__device__ __forceinline__ u32 swz256(int row, int kb) {
    return (u32)(row * 256 + ((((kb >> 4) ^ (row & 7)) << 4) | (kb & 15)));
}
__device__ __forceinline__ u32 swz128(int row, int kb) {
    return (u32)(row * 128 + ((((kb >> 4) ^ (row & 7)) << 4) | (kb & 15)));
}

// ---------------------------------------------------------------------------
// Scratch device globals.
// ---------------------------------------------------------------------------
__device__ float g_h[(size_t)BL * H];
__device__ float g_r[B * H];
__device__ float g_rp[B * H];
// Pre-split, pre-swizzled weight part-tiles (3 parts):
// g_W1s: [c=4][p=3][16384]  tile = 64 n-rows x 128 k bf16, swz256 rows
// g_W2s: [c=4][p=3][16384]  tile = 128 n-rows x 64 k bf16, swz128 rows
__device__ unsigned char g_W1s[4 * 3 * 16384];
__device__ unsigned char g_W2s[4 * 3 * 16384];

// ---------------------------------------------------------------------------
// Prep: split3 + transpose + swizzle the weights.
// ---------------------------------------------------------------------------
__global__ void __launch_bounds__(256) prep_kernel(
    const float* __restrict__ W1, const float* __restrict__ W2)
{
    int idx = blockIdx.x * 256 + threadIdx.x;   // 65536 total
    __nv_bfloat16 pp[3];
    if (idx < H * 2 * H) {                      // W1: [k=128][n=256]
        int k = idx >> 8;
        int n = idx & 255;
        split3(W1[idx], pp);
        int c = n >> 6, nl = n & 63;
        u32 off = swz256(nl, 2 * k);
        unsigned char* base = g_W1s + (size_t)c * 49152 + off;
        #pragma unroll
        for (int p = 0; p < 3; p++)
            *(__nv_bfloat16*)(base + p * 16384) = pp[p];
    } else {                                    // W2: [k2=256][n=128]
        int j  = idx - H * 2 * H;
        int k2 = j >> 7;
        int n  = j & 127;
        split3(W2[j], pp);
        int c = k2 >> 6, kl = k2 & 63;
        u32 off = swz128(n, 2 * kl);
        unsigned char* base = g_W2s + (size_t)c * 49152 + off;
        #pragma unroll
        for (int p = 0; p < 3; p++)
            *(__nv_bfloat16*)(base + p * 16384) = pp[p];
    }
}

// Stage schedule: s = c*6 + g*3 + jj, W part j = 2-jj (smallest products first).
__device__ __forceinline__ const unsigned char* stage_src(int s) {
    int c = s / 6, g = (s / 3) % 2, jj = s % 3;
    int j = 2 - jj;
    return (g ? g_W2s : g_W1s) + (size_t)c * 49152 + (size_t)j * 16384;
}

// ---------------------------------------------------------------------------
// Encode via bf16 mma.sync, 3-way split (6 products). Math order identical to
// R9/R10 per output element (W parts j=2,1,0; A parts i descending; k16
// descending), but 512 threads / 16 warps (4x4 warp tile grid) for 4
// warps/SMSP latency hiding. Triple-buffered W stream, pipelined ldmatrix.
// SMEM (199168 B): E 3x32768 @0 | A2 3x16384 @98304 | W 3x16384 @147456
//                  consts @196608 (b1 256f, b2/g/b 128f each)
// ---------------------------------------------------------------------------
#define EO       0
#define EPART    32768
#define A2O      98304
#define A2PART   16384
#define WO       147456
#define CO       196608
#define ENC_SMEM 199168

__global__ void __launch_bounds__(512, 1) encode_mma_kernel(
    const int* __restrict__ seq, const float* __restrict__ embed,
    const float* __restrict__ b1, const float* __restrict__ b2,
    const float* __restrict__ gamma, const float* __restrict__ beta)
{
    extern __shared__ char smc[];
    const u32 sb = smem_u32(smc);
    float* b1s = (float*)(smc + CO);
    float* b2s = b1s + 256;
    float* gs  = b2s + 128;
    float* bs  = gs + 128;

    const int t    = threadIdx.x;
    const int lane = t & 31;
    const int w    = t >> 5;          // 0..15
    const int tile0 = blockIdx.x * TOK;

    // Kick off first weight-part load immediately (overlaps E gather).
    {
        const unsigned char* src = stage_src(0) + t * 32;
        u32 dst = sb + WO + t * 32;
        cp16(dst, src); cp16(dst + 16, src + 16);
        asm volatile("cp.async.commit_group;");
    }

    if (t < 256) b1s[t] = b1[t];
    if (t < 128) { b2s[t] = b2[t]; gs[t] = gamma[t]; bs[t] = beta[t]; }

    // ---- gather + split3 E: four threads per token ----
    {
        int row = t >> 2, kh = t & 3;
        int tok = seq[tile0 + row];
        const float4* er = (const float4*)(embed + (size_t)tok * H) + kh * 8;
        #pragma unroll 4
        for (int i = 0; i < 8; i++) {
            float4 v = er[i];
            int col0 = kh * 32 + 4 * i;
            u32 offA = swz256(row, 2 * col0);
            __nv_bfloat16 px[3], py[3];
            split3(v.x, px); split3(v.y, py);
            #pragma unroll
            for (int p = 0; p < 3; p++)
                *(u32*)(smc + EO + p * EPART + offA) = pack_bf2(px[p], py[p]);
            split3(v.z, px); split3(v.w, py);
            #pragma unroll
            for (int p = 0; p < 3; p++)
                *(u32*)(smc + EO + p * EPART + offA + 4) = pack_bf2(px[p], py[p]);
        }
    }

    const int m0   = (w >> 2) * 32;       // 4 m-groups of 32 rows
    const int n0g1 = (w & 3) * 16;        // GEMM1: 16 cols per warp
    const int n0g2 = (w & 3) * 32;        // GEMM2: 32 cols per warp
    const int lg   = lane >> 3;
    const int rsel = (lane & 7) + ((lg & 1) << 3);
    const int kbs  = (lg >> 1) << 4;
    const int frow = lane >> 2;
    const int fcol = 2 * (lane & 3);

    float c1[2][2][4];                    // 2 m-tiles x 2 n-tiles (8 cols)
    float c2[2][4][4];                    // 2 m-tiles x 4 n-tiles
    #pragma unroll
    for (int mt = 0; mt < 2; mt++)
        #pragma unroll
        for (int nt = 0; nt < 4; nt++)
            #pragma unroll
            for (int jj = 0; jj < 4; jj++) c2[mt][nt][jj] = 0.f;

    // ---- 24 stages: chunk c x {GEMM1 parts j=2,1,0 ; GEMM2 parts j=2,1,0} ----
    for (int s = 0; s < 24; s++) {
        const int jj  = s % 3;       // stream index
        const int j   = 2 - jj;      // W part (2 first, 0 = dominant last)
        const int g   = (s / 3) % 2;
        const int buf = s % 3;

        // Prefetch next stage's W part into the third buffer.
        if (s < 23) {
            const unsigned char* src = stage_src(s + 1) + t * 32;
            u32 dst = sb + WO + ((s + 1) % 3) * 16384 + t * 32;
            cp16(dst, src); cp16(dst + 16, src + 16);
            asm volatile("cp.async.commit_group;");
            asm volatile("cp.async.wait_group 1;");
        } else {
            asm volatile("cp.async.wait_group 0;");
        }
        __syncthreads();   // stage-s weight part visible; prev compute drained

        const u32 Bb = sb + WO + buf * 16384;

        if (g == 0) {
            // ---------------- GEMM1: C1 += E_i @ W1c_j^T ----------------
            if (jj == 0) {
                #pragma unroll
                for (int mt = 0; mt < 2; mt++)
                    #pragma unroll
                    for (int nt = 0; nt < 2; nt++)
                        #pragma unroll
                        for (int q = 0; q < 4; q++) c1[mt][nt][q] = 0.f;
            }
            for (int i = 2 - j; i >= 0; i--) {          // small first, a0 last
                const u32 Ab = sb + EO + i * EPART;
                u32 af[2][2][4], qf[2][4];              // [pipe buf][...]
                {   // preload k16 = 7
                    const int kb = 7 * 32 + kbs;
                    ldsm_x4(af[0][0], Ab + swz256(m0 + rsel, kb));
                    ldsm_x4(af[0][1], Ab + swz256(m0 + 16 + rsel, kb));
                    ldsm_x4(qf[0], Bb + swz256(n0g1 + rsel, kb));
                }
                #pragma unroll
                for (int k16 = 7; k16 >= 0; k16--) {    // reversed k-chunks
                    const int cur = (7 - k16) & 1;
                    if (k16 > 0) {                      // prefetch next frags
                        const int kb2 = (k16 - 1) * 32 + kbs;
                        ldsm_x4(af[cur ^ 1][0], Ab + swz256(m0 + rsel, kb2));
                        ldsm_x4(af[cur ^ 1][1], Ab + swz256(m0 + 16 + rsel, kb2));
                        ldsm_x4(qf[cur ^ 1], Bb + swz256(n0g1 + rsel, kb2));
                    }
                    #pragma unroll
                    for (int mt = 0; mt < 2; mt++)
                        #pragma unroll
                        for (int nt = 0; nt < 2; nt++)
                            mma16816(c1[mt][nt], af[cur][mt],
                                     qf[cur][nt], qf[cur][2 + nt]);
                }
            }
            if (jj == 2) {
                // ---- bias + relu + split3 -> A2 parts ----
                const int c = s / 6;
                #pragma unroll
                for (int mt = 0; mt < 2; mt++) {
                    #pragma unroll
                    for (int nt = 0; nt < 2; nt++) {
                        int col = n0g1 + nt * 8 + fcol;
                        float bb0 = b1s[c * 64 + col];
                        float bb1 = b1s[c * 64 + col + 1];
                        #pragma unroll
                        for (int half = 0; half < 2; half++) {
                            int row = m0 + mt * 16 + frow + half * 8;
                            float h0 = fmaxf(c1[mt][nt][2 * half + 0] + bb0, 0.f);
                            float h1 = fmaxf(c1[mt][nt][2 * half + 1] + bb1, 0.f);
                            __nv_bfloat16 px[3], py[3];
                            split3(h0, px); split3(h1, py);
                            u32 off = swz128(row, 2 * col);
                            #pragma unroll
                            for (int p = 0; p < 3; p++)
                                *(u32*)(smc + A2O + p * A2PART + off) =
                                    pack_bf2(px[p], py[p]);
                        }
                    }
                }
            }
        } else {
            // ---------------- GEMM2: C2 += A2_i @ W2c_j^T ----------------
            for (int i = 2 - j; i >= 0; i--) {
                const u32 Ab = sb + A2O + i * A2PART;
                u32 af[2][2][4], qf[2][2][4];
                {   // preload k16 = 3
                    const int kb = 3 * 32 + kbs;
                    ldsm_x4(af[0][0], Ab + swz128(m0 + rsel, kb));
                    ldsm_x4(af[0][1], Ab + swz128(m0 + 16 + rsel, kb));
                    ldsm_x4(qf[0][0], Bb + swz128(n0g2 + rsel, kb));
                    ldsm_x4(qf[0][1], Bb + swz128(n0g2 + 16 + rsel, kb));
                }
                #pragma unroll
                for (int k16 = 3; k16 >= 0; k16--) {
                    const int cur = (3 - k16) & 1;
                    if (k16 > 0) {
                        const int kb2 = (k16 - 1) * 32 + kbs;
                        ldsm_x4(af[cur ^ 1][0], Ab + swz128(m0 + rsel, kb2));
                        ldsm_x4(af[cur ^ 1][1], Ab + swz128(m0 + 16 + rsel, kb2));
                        ldsm_x4(qf[cur ^ 1][0], Bb + swz128(n0g2 + rsel, kb2));
                        ldsm_x4(qf[cur ^ 1][1], Bb + swz128(n0g2 + 16 + rsel, kb2));
                    }
                    #pragma unroll
                    for (int mt = 0; mt < 2; mt++)
                        #pragma unroll
                        for (int nt = 0; nt < 4; nt++)
                            mma16816(c2[mt][nt], af[cur][mt],
                                     qf[cur][nt >> 1][nt & 1],
                                     qf[cur][nt >> 1][2 + (nt & 1)]);
                }
            }
        }
    }

    // ---- epilogue: y = ff + b2 + e (e from 3 SMEM parts) ----
    #pragma unroll
    for (int mt = 0; mt < 2; mt++) {
        #pragma unroll
        for (int nt = 0; nt < 4; nt++) {
            int col = n0g2 + nt * 8 + fcol;
            float bb0 = b2s[col], bb1 = b2s[col + 1];
            #pragma unroll
            for (int half = 0; half < 2; half++) {
                int row = m0 + mt * 16 + frow + half * 8;
                u32 off = swz256(row, 2 * col);
                float e0 = 0.f, e1 = 0.f;
                #pragma unroll
                for (int p = 2; p >= 0; p--) {
                    u32 ev = *(u32*)(smc + EO + p * EPART + off);
                    __nv_bfloat162 eb = *(__nv_bfloat162*)&ev;
                    e0 += __bfloat162float(eb.x);
                    e1 += __bfloat162float(eb.y);
                }
                c2[mt][nt][2 * half + 0] += bb0 + e0;
                c2[mt][nt][2 * half + 1] += bb1 + e1;
            }
        }
    }
    __syncthreads();   // all E reads done before overwrite

    // ---- y -> ySM (stride 132 floats, reuses E region), LN, write g_h ----
    float* ySM = (float*)(smc + EO);
    float* muS = (float*)(smc + A2O);
    float* ivS = muS + 128;
    #pragma unroll
    for (int mt = 0; mt < 2; mt++) {
        #pragma unroll
        for (int nt = 0; nt < 4; nt++) {
            int col = n0g2 + nt * 8 + fcol;
            #pragma unroll
            for (int half = 0; half < 2; half++) {
                int row = m0 + mt * 16 + frow + half * 8;
                *(float2*)(ySM + row * 132 + col) =
                    make_float2(c2[mt][nt][2 * half + 0], c2[mt][nt][2 * half + 1]);
            }
        }
    }
    __syncthreads();

    if (t < 128) {
        const float4* yr = (const float4*)(ySM + t * 132);
        float s = 0.f, q = 0.f;
        #pragma unroll 8
        for (int jj = 0; jj < 32; jj++) {
            float4 y = yr[jj];
            s += (y.x + y.y) + (y.z + y.w);
            q += y.x * y.x + y.y * y.y + y.z * y.z + y.w * y.w;
        }
        float mu  = s * (1.0f / H);
        float var = q * (1.0f / H) - mu * mu;
        muS[t] = mu;
        ivS[t] = rsqrtf(var + 1e-5f);
    }
    __syncthreads();

    #pragma unroll
    for (int i = t; i < 128 * 32; i += 512) {
        int row = i >> 5, jj = i & 31;
        float4 y = ((const float4*)(ySM + row * 132))[jj];
        float mu = muS[row], iv = ivS[row];
        float4 g4 = ((const float4*)gs)[jj];
        float4 b4 = ((const float4*)bs)[jj];
        float4 o4;
        o4.x = (y.x - mu) * iv * g4.x + b4.x;
        o4.y = (y.y - mu) * iv * g4.y + b4.y;
        o4.z = (y.z - mu) * iv * g4.z + b4.z;
        o4.w = (y.w - mu) * iv * g4.w + b4.w;
        ((float4*)(g_h + (size_t)(tile0 + row) * H))[jj] = o4;
    }
}

// ---------------------------------------------------------------------------
// Scan: one CTA per batch (unchanged from R5/R9 — bitwise-stable numerics).
// ---------------------------------------------------------------------------
__global__ void __launch_bounds__(128, 2) scan_kernel()
{
    const int b = blockIdx.x;
    const int tid = threadIdx.x;
    const int lane = tid & 31;
    const int wid = tid >> 5;

    __shared__ float ks[2][H];
    __shared__ float red_kk[4];
    __shared__ float red_ee[4];

    float2 Mr[64];
    #pragma unroll
    for (int q = 0; q < 64; q++) Mr[q] = make_float2(0.f, 0.f);

    const float* hb = g_h + (size_t)b * L * H;
    float kv_next = hb[tid];

    for (int t = 0; t < L - 1; t++) {
        const int buf = t & 1;
        const float kv = kv_next;
        ks[buf][tid] = kv;

        float p = kv * kv;
        #pragma unroll
        for (int o = 16; o; o >>= 1) p += __shfl_xor_sync(0xffffffffu, p, o);
        if (lane == 0) red_kk[wid] = p;
        __syncthreads();

        kv_next = hb[(size_t)(t + 1) * H + tid];
        const float kk = (red_kk[0] + red_kk[1]) + (red_kk[2] + red_kk[3]);

        const float4* k4 = (const float4*)ks[buf];
        float2 a0 = make_float2(0.f, 0.f), a1 = a0, a2 = a0, a3 = a0;
        #pragma unroll
        for (int q = 0; q < 32; q += 2) {
            float4 ka = k4[q];
            float4 kb = k4[q + 1];
            const float2* kap = reinterpret_cast<const float2*>(&ka);
            const float2* kbp = reinterpret_cast<const float2*>(&kb);
            a0 = ffma2(Mr[2 * q + 0], kap[0], a0);
            a1 = ffma2(Mr[2 * q + 1], kap[1], a1);
            a2 = ffma2(Mr[2 * q + 2], kbp[0], a2);
            a3 = ffma2(Mr[2 * q + 3], kbp[1], a3);
        }
        const float vp = ((a0.x + a0.y) + (a1.x + a1.y))
                       + ((a2.x + a2.y) + (a3.x + a3.y));
        const float err = kv - vp / (kk + 1e-6f);

        float pe = err * err;
        #pragma unroll
        for (int o = 16; o; o >>= 1) pe += __shfl_xor_sync(0xffffffffu, pe, o);
        if (lane == 0) red_ee[wid] = pe;
        __syncthreads();
        const float ee = (red_ee[0] + red_ee[1]) + (red_ee[2] + red_ee[3]);

        if (ee > 0.16f * kk) {
            const float2 e2 = make_float2(err, err);
            #pragma unroll
            for (int q = 0; q < 32; q++) {
                float4 kq = k4[q];
                const float2* kp = reinterpret_cast<const float2*>(&kq);
                Mr[2 * q + 0] = ffma2(e2, kp[0], Mr[2 * q + 0]);
                Mr[2 * q + 1] = ffma2(e2, kp[1], Mr[2 * q + 1]);
            }
        }
    }

    ks[1][tid] = kv_next;
    __syncthreads();
    const float4* k4 = (const float4*)ks[1];
    float2 a0 = make_float2(0.f, 0.f), a1 = a0, a2 = a0, a3 = a0;
    #pragma unroll
    for (int q = 0; q < 32; q += 2) {
        float4 ka = k4[q];
        float4 kb = k4[q + 1];
        const float2* kap = reinterpret_cast<const float2*>(&ka);
        const float2* kbp = reinterpret_cast<const float2*>(&kb);
        a0 = ffma2(Mr[2 * q + 0], kap[0], a0);
        a1 = ffma2(Mr[2 * q + 1], kap[1], a1);
        a2 = ffma2(Mr[2 * q + 2], kbp[0], a2);
        a3 = ffma2(Mr[2 * q + 3], kbp[1], a3);
    }
    g_r[b * H + tid] = ((a0.x + a0.y) + (a1.x + a1.y))
                     + ((a2.x + a2.y) + (a3.x + a3.y));
}

// ---------------------------------------------------------------------------
__global__ void rp_kernel(const float* __restrict__ Wrp, const float* __restrict__ brp)
{
    const int b = blockIdx.x;
    const int i = threadIdx.x;
    __shared__ float rb[H];
    rb[i] = g_r[b * H + i];
    __syncthreads();
    float acc = brp[i];
    #pragma unroll 8
    for (int j = 0; j < H; j++) acc += rb[j] * Wrp[j * H + i];
    g_rp[b * H + i] = acc;
}

// ---------------------------------------------------------------------------
__global__ void __launch_bounds__(256) out_kernel(
    const float* __restrict__ Wout, const float* __restrict__ bout,
    float* __restrict__ out)
{
    __shared__ float rp_sm[64 * H];
    const int t = threadIdx.x;
    const int v0 = blockIdx.x * 128;
    const int b0 = blockIdx.y * 64;

    #pragma unroll
    for (int i = 0; i < 32; i++) {
        int idx = i * 256 + t;
        rp_sm[idx] = g_rp[b0 * H + idx];
    }
    __syncthreads();

    const int tx = t & 31;
    const int ty = t >> 5;
    const int m0 = ty * 8;
    const int n  = v0 + tx * 4;

    float2 acc[8][2];
    #pragma unroll
    for (int i = 0; i < 8; i++) {
        acc[i][0] = make_float2(0.f, 0.f);
        acc[i][1] = make_float2(0.f, 0.f);
    }

    #pragma unroll 2
    for (int k = 0; k < H; k++) {
        float4 wv = *(const float4*)(Wout + (size_t)k * V + n);
        const float2* wp = reinterpret_cast<const float2*>(&wv);
        #pragma unroll
        for (int i = 0; i < 8; i++) {
            float hv = rp_sm[(m0 + i) * H + k];
            float2 h2 = make_float2(hv, hv);
            acc[i][0] = ffma2(h2, wp[0], acc[i][0]);
            acc[i][1] = ffma2(h2, wp[1], acc[i][1]);
        }
    }
    const float4 bo = *(const float4*)(bout + n);
    #pragma unroll
    for (int i = 0; i < 8; i++) {
        float4 o;
        o.x = acc[i][0].x + bo.x; o.y = acc[i][0].y + bo.y;
        o.z = acc[i][1].x + bo.z; o.w = acc[i][1].y + bo.w;
        *(float4*)(out + (size_t)(b0 + m0 + i) * V + n) = o;
    }
}

// ---------------------------------------------------------------------------
extern "C" void kernel_launch(void* const* d_in, const int* in_sizes, int n_in,
                              void* d_out, int out_size)
{
    const int*   seq   = (const int*)  d_in[0];
    const float* embed = (const float*)d_in[1];
    const float* W1    = (const float*)d_in[2];
    const float* b1    = (const float*)d_in[3];
    const float* W2    = (const float*)d_in[4];
    const float* b2    = (const float*)d_in[5];
    const float* gamma = (const float*)d_in[6];
    const float* beta  = (const float*)d_in[7];
    const float* Wrp   = (const float*)d_in[8];
    const float* brp   = (const float*)d_in[9];
    const float* Wout  = (const float*)d_in[10];
    const float* bout  = (const float*)d_in[11];
    float* out = (float*)d_out;

    cudaFuncSetAttribute(encode_mma_kernel,
                         cudaFuncAttributeMaxDynamicSharedMemorySize, ENC_SMEM);

    prep_kernel<<<256, 256>>>(W1, W2);
    encode_mma_kernel<<<BL / TOK, 512, ENC_SMEM>>>(seq, embed, b1, b2, gamma, beta);
    scan_kernel<<<B, 128>>>();
    rp_kernel<<<B, H>>>(Wrp, brp);
    dim3 og(V / 128, B / 64);
    out_kernel<<<og, 256>>>(Wout, bout, out);
}

// round 12
// speedup vs baseline: 1.0299x; 1.0299x over previous
#include <cuda_runtime.h>
#include <cuda_bf16.h>
#include <cstdint>
#include <cstddef>

#define B 256
#define L 2048
#define H 128
#define V 32000
#define BL (B * L)
#define TOK 128

typedef unsigned long long u64;
typedef uint32_t u32;

// ---------------------------------------------------------------------------
// helpers
// ---------------------------------------------------------------------------
__device__ __forceinline__ u32 smem_u32(const void* p) {
    return (u32)__cvta_generic_to_shared(p);
}

__device__ __forceinline__ void ldsm_x4(u32* r, u32 addr) {
    asm volatile("ldmatrix.sync.aligned.m8n8.x4.shared.b16 {%0,%1,%2,%3}, [%4];"
                 : "=r"(r[0]), "=r"(r[1]), "=r"(r[2]), "=r"(r[3]) : "r"(addr));
}

__device__ __forceinline__ void mma16816(float* d, const u32* a, u32 b0, u32 b1) {
    asm volatile(
        "mma.sync.aligned.m16n8k16.row.col.f32.bf16.bf16.f32 "
        "{%0,%1,%2,%3}, {%4,%5,%6,%7}, {%8,%9}, {%0,%1,%2,%3};"
        : "+f"(d[0]), "+f"(d[1]), "+f"(d[2]), "+f"(d[3])
        : "r"(a[0]), "r"(a[1]), "r"(a[2]), "r"(a[3]), "r"(b0), "r"(b1));
}

__device__ __forceinline__ void cp16(u32 dst, const void* src) {
    asm volatile("cp.async.cg.shared.global [%0], [%1], 16;" :: "r"(dst), "l"(src));
}

// Packed dual-FMA (scan/out kernels).
__device__ __forceinline__ float2 ffma2(float2 a, float2 b, float2 c) {
    float2 d;
    asm("fma.rn.f32x2 %0, %1, %2, %3;"
        : "=l"(*(u64*)&d)
        : "l"(*(u64*)&a), "l"(*(u64*)&b), "l"(*(u64*)&c));
    return d;
}

// 3-way bf16 split: x = a0+a1+a2 + O(2^-27 * x)
__device__ __forceinline__ void split3(float x, __nv_bfloat16* a) {
    a[0] = __float2bfloat16(x);
    float r = x - __bfloat162float(a[0]);
    a[1] = __float2bfloat16(r);  r -= __bfloat162float(a[1]);
    a[2] = __float2bfloat16(r);
}
__device__ __forceinline__ u32 pack_bf2(__nv_bfloat16 lo, __nv_bfloat16 hi) {
    __nv_bfloat162 p;
    p.x = lo; p.y = hi;
    return *(u32*)&p;
}

// XOR chunk swizzles: conflict-free ldmatrix on natural row strides.
__device__ __forceinline__ u32 swz256(int row, int kb) {
    return (u32)(row * 256 + ((((kb >> 4) ^ (row & 7)) << 4) | (kb & 15)));
}
__device__ __forceinline__ u32 swz128(int row, int kb) {
    return (u32)(row * 128 + ((((kb >> 4) ^ (row & 7)) << 4) | (kb & 15)));
}

// ---------------------------------------------------------------------------
// Scratch device globals.
// ---------------------------------------------------------------------------
__device__ float g_h[(size_t)BL * H];
__device__ float g_r[B * H];
__device__ float g_rp[B * H];
__device__ float g_kk[B * L];   // ||k_t||^2 (bitwise-matching reduction tree)
__device__ float g_kd[B * L];   // k_t . k_{t+1}
// Pre-split, pre-swizzled weight part-tiles (3 parts):
__device__ unsigned char g_W1s[4 * 3 * 16384];
__device__ unsigned char g_W2s[4 * 3 * 16384];

// ---------------------------------------------------------------------------
// Prep: split3 + transpose + swizzle the weights.
// ---------------------------------------------------------------------------
__global__ void __launch_bounds__(256) prep_kernel(
    const float* __restrict__ W1, const float* __restrict__ W2)
{
    int idx = blockIdx.x * 256 + threadIdx.x;   // 65536 total
    __nv_bfloat16 pp[3];
    if (idx < H * 2 * H) {                      // W1: [k=128][n=256]
        int k = idx >> 8;
        int n = idx & 255;
        split3(W1[idx], pp);
        int c = n >> 6, nl = n & 63;
        u32 off = swz256(nl, 2 * k);
        unsigned char* base = g_W1s + (size_t)c * 49152 + off;
        #pragma unroll
        for (int p = 0; p < 3; p++)
            *(__nv_bfloat16*)(base + p * 16384) = pp[p];
    } else {                                    // W2: [k2=256][n=128]
        int j  = idx - H * 2 * H;
        int k2 = j >> 7;
        int n  = j & 127;
        split3(W2[j], pp);
        int c = k2 >> 6, kl = k2 & 63;
        u32 off = swz128(n, 2 * kl);
        unsigned char* base = g_W2s + (size_t)c * 49152 + off;
        #pragma unroll
        for (int p = 0; p < 3; p++)
            *(__nv_bfloat16*)(base + p * 16384) = pp[p];
    }
}

// Stage schedule: s = c*6 + g*3 + jj, W part j = 2-jj (smallest products first).
__device__ __forceinline__ const unsigned char* stage_src(int s) {
    int c = s / 6, g = (s / 3) % 2, jj = s % 3;
    int j = 2 - jj;
    return (g ? g_W2s : g_W1s) + (size_t)c * 49152 + (size_t)j * 16384;
}

// ---------------------------------------------------------------------------
// Encode: R10 configuration (256 threads, triple-buffered W, pipelined ldsm).
// SMEM (199168 B): E 3x32768 @0 | A2 3x16384 @98304 | W 3x16384 @147456
// ---------------------------------------------------------------------------
#define EO       0
#define EPART    32768
#define A2O      98304
#define A2PART   16384
#define WO       147456
#define CO       196608
#define ENC_SMEM 199168

__global__ void __launch_bounds__(256, 1) encode_mma_kernel(
    const int* __restrict__ seq, const float* __restrict__ embed,
    const float* __restrict__ b1, const float* __restrict__ b2,
    const float* __restrict__ gamma, const float* __restrict__ beta)
{
    extern __shared__ char smc[];
    const u32 sb = smem_u32(smc);
    float* b1s = (float*)(smc + CO);
    float* b2s = b1s + 256;
    float* gs  = b2s + 128;
    float* bs  = gs + 128;

    const int t    = threadIdx.x;
    const int lane = t & 31;
    const int w    = t >> 5;
    const int tile0 = blockIdx.x * TOK;

    {
        const unsigned char* src = stage_src(0) + t * 64;
        u32 dst = sb + WO + t * 64;
        cp16(dst, src); cp16(dst + 16, src + 16);
        cp16(dst + 32, src + 32); cp16(dst + 48, src + 48);
        asm volatile("cp.async.commit_group;");
    }

    b1s[t] = b1[t];
    if (t < 128) { b2s[t] = b2[t]; gs[t] = gamma[t]; bs[t] = beta[t]; }

    {
        int row = t >> 1, kh = t & 1;
        int tok = seq[tile0 + row];
        const float4* er = (const float4*)(embed + (size_t)tok * H) + kh * 16;
        #pragma unroll 4
        for (int i = 0; i < 16; i++) {
            float4 v = er[i];
            int col0 = kh * 64 + 4 * i;
            u32 offA = swz256(row, 2 * col0);
            __nv_bfloat16 px[3], py[3];
            split3(v.x, px); split3(v.y, py);
            #pragma unroll
            for (int p = 0; p < 3; p++)
                *(u32*)(smc + EO + p * EPART + offA) = pack_bf2(px[p], py[p]);
            split3(v.z, px); split3(v.w, py);
            #pragma unroll
            for (int p = 0; p < 3; p++)
                *(u32*)(smc + EO + p * EPART + offA + 4) = pack_bf2(px[p], py[p]);
        }
    }

    const int m0   = (w >> 1) * 32;
    const int n0g1 = (w & 1) * 32;
    const int n0g2 = (w & 1) * 64;
    const int lg   = lane >> 3;
    const int rsel = (lane & 7) + ((lg & 1) << 3);
    const int kbs  = (lg >> 1) << 4;
    const int frow = lane >> 2;
    const int fcol = 2 * (lane & 3);

    float c1[2][4][4];
    float c2[2][8][4];
    #pragma unroll
    for (int mt = 0; mt < 2; mt++)
        #pragma unroll
        for (int nt = 0; nt < 8; nt++)
            #pragma unroll
            for (int jj = 0; jj < 4; jj++) c2[mt][nt][jj] = 0.f;

    for (int s = 0; s < 24; s++) {
        const int jj  = s % 3;
        const int j   = 2 - jj;
        const int g   = (s / 3) % 2;
        const int buf = s % 3;

        if (s < 23) {
            const unsigned char* src = stage_src(s + 1) + t * 64;
            u32 dst = sb + WO + ((s + 1) % 3) * 16384 + t * 64;
            cp16(dst, src); cp16(dst + 16, src + 16);
            cp16(dst + 32, src + 32); cp16(dst + 48, src + 48);
            asm volatile("cp.async.commit_group;");
            asm volatile("cp.async.wait_group 1;");
        } else {
            asm volatile("cp.async.wait_group 0;");
        }
        __syncthreads();

        const u32 Bb = sb + WO + buf * 16384;

        if (g == 0) {
            if (jj == 0) {
                #pragma unroll
                for (int mt = 0; mt < 2; mt++)
                    #pragma unroll
                    for (int nt = 0; nt < 4; nt++)
                        #pragma unroll
                        for (int q = 0; q < 4; q++) c1[mt][nt][q] = 0.f;
            }
            for (int i = 2 - j; i >= 0; i--) {
                const u32 Ab = sb + EO + i * EPART;
                u32 af[2][2][4], qf[2][2][4];
                {
                    const int kb = 7 * 32 + kbs;
                    ldsm_x4(af[0][0], Ab + swz256(m0 + rsel, kb));
                    ldsm_x4(af[0][1], Ab + swz256(m0 + 16 + rsel, kb));
                    ldsm_x4(qf[0][0], Bb + swz256(n0g1 + rsel, kb));
                    ldsm_x4(qf[0][1], Bb + swz256(n0g1 + 16 + rsel, kb));
                }
                #pragma unroll
                for (int k16 = 7; k16 >= 0; k16--) {
                    const int cur = (7 - k16) & 1;
                    if (k16 > 0) {
                        const int kb2 = (k16 - 1) * 32 + kbs;
                        ldsm_x4(af[cur ^ 1][0], Ab + swz256(m0 + rsel, kb2));
                        ldsm_x4(af[cur ^ 1][1], Ab + swz256(m0 + 16 + rsel, kb2));
                        ldsm_x4(qf[cur ^ 1][0], Bb + swz256(n0g1 + rsel, kb2));
                        ldsm_x4(qf[cur ^ 1][1], Bb + swz256(n0g1 + 16 + rsel, kb2));
                    }
                    #pragma unroll
                    for (int mt = 0; mt < 2; mt++)
                        #pragma unroll
                        for (int nt = 0; nt < 4; nt++)
                            mma16816(c1[mt][nt], af[cur][mt],
                                     qf[cur][nt >> 1][nt & 1],
                                     qf[cur][nt >> 1][2 + (nt & 1)]);
                }
            }
            if (jj == 2) {
                const int c = s / 6;
                #pragma unroll
                for (int mt = 0; mt < 2; mt++) {
                    #pragma unroll
                    for (int nt = 0; nt < 4; nt++) {
                        int col = n0g1 + nt * 8 + fcol;
                        float bb0 = b1s[c * 64 + col];
                        float bb1 = b1s[c * 64 + col + 1];
                        #pragma unroll
                        for (int half = 0; half < 2; half++) {
                            int row = m0 + mt * 16 + frow + half * 8;
                            float h0 = fmaxf(c1[mt][nt][2 * half + 0] + bb0, 0.f);
                            float h1 = fmaxf(c1[mt][nt][2 * half + 1] + bb1, 0.f);
                            __nv_bfloat16 px[3], py[3];
                            split3(h0, px); split3(h1, py);
                            u32 off = swz128(row, 2 * col);
                            #pragma unroll
                            for (int p = 0; p < 3; p++)
                                *(u32*)(smc + A2O + p * A2PART + off) =
                                    pack_bf2(px[p], py[p]);
                        }
                    }
                }
            }
        } else {
            for (int i = 2 - j; i >= 0; i--) {
                const u32 Ab = sb + A2O + i * A2PART;
                u32 af[2][2][4], qf[2][4][4];
                {
                    const int kb = 3 * 32 + kbs;
                    ldsm_x4(af[0][0], Ab + swz128(m0 + rsel, kb));
                    ldsm_x4(af[0][1], Ab + swz128(m0 + 16 + rsel, kb));
                    #pragma unroll
                    for (int nt2 = 0; nt2 < 4; nt2++)
                        ldsm_x4(qf[0][nt2], Bb + swz128(n0g2 + nt2 * 16 + rsel, kb));
                }
                #pragma unroll
                for (int k16 = 3; k16 >= 0; k16--) {
                    const int cur = (3 - k16) & 1;
                    if (k16 > 0) {
                        const int kb2 = (k16 - 1) * 32 + kbs;
                        ldsm_x4(af[cur ^ 1][0], Ab + swz128(m0 + rsel, kb2));
                        ldsm_x4(af[cur ^ 1][1], Ab + swz128(m0 + 16 + rsel, kb2));
                        #pragma unroll
                        for (int nt2 = 0; nt2 < 4; nt2++)
                            ldsm_x4(qf[cur ^ 1][nt2],
                                    Bb + swz128(n0g2 + nt2 * 16 + rsel, kb2));
                    }
                    #pragma unroll
                    for (int mt = 0; mt < 2; mt++)
                        #pragma unroll
                        for (int nt = 0; nt < 8; nt++)
                            mma16816(c2[mt][nt], af[cur][mt],
                                     qf[cur][nt >> 1][nt & 1],
                                     qf[cur][nt >> 1][2 + (nt & 1)]);
                }
            }
        }
    }

    #pragma unroll
    for (int mt = 0; mt < 2; mt++) {
        #pragma unroll
        for (int nt = 0; nt < 8; nt++) {
            int col = n0g2 + nt * 8 + fcol;
            float bb0 = b2s[col], bb1 = b2s[col + 1];
            #pragma unroll
            for (int half = 0; half < 2; half++) {
                int row = m0 + mt * 16 + frow + half * 8;
                u32 off = swz256(row, 2 * col);
                float e0 = 0.f, e1 = 0.f;
                #pragma unroll
                for (int p = 2; p >= 0; p--) {
                    u32 ev = *(u32*)(smc + EO + p * EPART + off);
                    __nv_bfloat162 eb = *(__nv_bfloat162*)&ev;
                    e0 += __bfloat162float(eb.x);
                    e1 += __bfloat162float(eb.y);
                }
                c2[mt][nt][2 * half + 0] += bb0 + e0;
                c2[mt][nt][2 * half + 1] += bb1 + e1;
            }
        }
    }
    __syncthreads();

    float* ySM = (float*)(smc + EO);
    float* muS = (float*)(smc + A2O);
    float* ivS = muS + 128;
    #pragma unroll
    for (int mt = 0; mt < 2; mt++) {
        #pragma unroll
        for (int nt = 0; nt < 8; nt++) {
            int col = n0g2 + nt * 8 + fcol;
            #pragma unroll
            for (int half = 0; half < 2; half++) {
                int row = m0 + mt * 16 + frow + half * 8;
                *(float2*)(ySM + row * 132 + col) =
                    make_float2(c2[mt][nt][2 * half + 0], c2[mt][nt][2 * half + 1]);
            }
        }
    }
    __syncthreads();

    if (t < 128) {
        const float4* yr = (const float4*)(ySM + t * 132);
        float s = 0.f, q = 0.f;
        #pragma unroll 8
        for (int jj = 0; jj < 32; jj++) {
            float4 y = yr[jj];
            s += (y.x + y.y) + (y.z + y.w);
            q += y.x * y.x + y.y * y.y + y.z * y.z + y.w * y.w;
        }
        float mu  = s * (1.0f / H);
        float var = q * (1.0f / H) - mu * mu;
        muS[t] = mu;
        ivS[t] = rsqrtf(var + 1e-5f);
    }
    __syncthreads();

    #pragma unroll
    for (int i = t; i < 128 * 32; i += 256) {
        int row = i >> 5, jj = i & 31;
        float4 y = ((const float4*)(ySM + row * 132))[jj];
        float mu = muS[row], iv = ivS[row];
        float4 g4 = ((const float4*)gs)[jj];
        float4 b4 = ((const float4*)bs)[jj];
        float4 o4;
        o4.x = (y.x - mu) * iv * g4.x + b4.x;
        o4.y = (y.y - mu) * iv * g4.y + b4.y;
        o4.z = (y.z - mu) * iv * g4.z + b4.z;
        o4.w = (y.w - mu) * iv * g4.w + b4.w;
        ((float4*)(g_h + (size_t)(tile0 + row) * H))[jj] = o4;
    }
}

// ---------------------------------------------------------------------------
// Norms precompute: kk[t] = ||k_t||^2 with the EXACT reduction tree the scan
// used (butterfly 16..1 then (r0+r1)+(r2+r3)); kd[t] = k_t . k_{t+1}.
// Grid (B, 16), 128 threads; each CTA covers 128 timesteps.
// ---------------------------------------------------------------------------
__global__ void __launch_bounds__(128) norms_kernel()
{
    const int b = blockIdx.x;
    const int t0 = blockIdx.y * 128;
    const int tid = threadIdx.x;
    const int lane = tid & 31;
    const int wid = tid >> 5;

    __shared__ float redk[2][4], redd[2][4];

    const float* hb = g_h + (size_t)b * L * H;
    float kv = hb[(size_t)t0 * H + tid];

    for (int tt = 0; tt < 128; tt++) {
        const int t = t0 + tt;
        const int par = tt & 1;
        float kvn = (t + 1 < L) ? hb[(size_t)(t + 1) * H + tid] : 0.f;

        float p = kv * kv;
        float p2 = kv * kvn;
        #pragma unroll
        for (int o = 16; o; o >>= 1) {
            p  += __shfl_xor_sync(0xffffffffu, p, o);
            p2 += __shfl_xor_sync(0xffffffffu, p2, o);
        }
        if (lane == 0) { redk[par][wid] = p; redd[par][wid] = p2; }
        __syncthreads();
        if (tid == 0) {
            g_kk[b * L + t] = (redk[par][0] + redk[par][1])
                            + (redk[par][2] + redk[par][3]);
            g_kd[b * L + t] = (redd[par][0] + redd[par][1])
                            + (redd[par][2] + redd[par][3]);
        }
        kv = kvn;
    }
}

// ---------------------------------------------------------------------------
// Scan: paired delta-rule steps. Even-step numerics bitwise-identical to R10
// (same M, same kv, same kk bits, same dot tree); odd steps use the rank-1
// correction vp1 = u1 + gate0*err0*kdot. Updates fused in sequential rounding
// order. One CTA per batch, 128 threads.
// ---------------------------------------------------------------------------
__global__ void __launch_bounds__(128, 2) scan_kernel()
{
    const int b = blockIdx.x;
    const int tid = threadIdx.x;
    const int lane = tid & 31;
    const int wid = tid >> 5;

    __shared__ float ks[2][2][H];     // [pair parity][0/1]
    __shared__ float red0[4], red1[4];

    float2 Mr[64];
    #pragma unroll
    for (int q = 0; q < 64; q++) Mr[q] = make_float2(0.f, 0.f);

    const float* hb  = g_h + (size_t)b * L * H;
    const float* kkp = g_kk + (size_t)b * L;
    const float* kdp = g_kd + (size_t)b * L;

    float kv0 = hb[tid];
    float kv1 = hb[(size_t)H + tid];
    float kk0 = kkp[0];
    float kk1 = kkp[1];
    float kd01 = kdp[0];

    // 1023 pairs: t = 0,2,...,2044 ; leftover single step t = 2046.
    for (int pair = 0; pair < 1023; pair++) {
        const int par = pair & 1;
        ks[par][0][tid] = kv0;
        ks[par][1][tid] = kv1;
        __syncthreads();                                  // BAR-A (ks visible)

        // prefetch next pair
        const int t2 = 2 * pair + 2;
        float kvn0 = hb[(size_t)t2 * H + tid];
        float kvn1 = hb[(size_t)(t2 + 1) * H + tid];
        float kkn0 = kkp[t2];
        float kkn1 = kkp[t2 + 1];
        float kdn  = kdp[t2];

        // dual MV: u0 = M.k0 (bitwise == R10 tree), u1 = M.k1
        const float4* k40 = (const float4*)ks[par][0];
        const float4* k41 = (const float4*)ks[par][1];
        float2 a0 = make_float2(0.f, 0.f), a1 = a0, a2 = a0, a3 = a0;
        float2 c0 = a0, c1_ = a0, c2_ = a0, c3 = a0;
        #pragma unroll
        for (int q = 0; q < 32; q += 2) {
            float4 ka = k40[q];
            float4 kb = k40[q + 1];
            float4 kc = k41[q];
            float4 kd_ = k41[q + 1];
            const float2* kap = reinterpret_cast<const float2*>(&ka);
            const float2* kbp = reinterpret_cast<const float2*>(&kb);
            const float2* kcp = reinterpret_cast<const float2*>(&kc);
            const float2* kdp_ = reinterpret_cast<const float2*>(&kd_);
            a0 = ffma2(Mr[2 * q + 0], kap[0], a0);
            a1 = ffma2(Mr[2 * q + 1], kap[1], a1);
            a2 = ffma2(Mr[2 * q + 2], kbp[0], a2);
            a3 = ffma2(Mr[2 * q + 3], kbp[1], a3);
            c0 = ffma2(Mr[2 * q + 0], kcp[0], c0);
            c1_ = ffma2(Mr[2 * q + 1], kcp[1], c1_);
            c2_ = ffma2(Mr[2 * q + 2], kdp_[0], c2_);
            c3 = ffma2(Mr[2 * q + 3], kdp_[1], c3);
        }
        const float u0 = ((a0.x + a0.y) + (a1.x + a1.y))
                       + ((a2.x + a2.y) + (a3.x + a3.y));
        const float u1 = ((c0.x + c0.y) + (c1_.x + c1_.y))
                       + ((c2_.x + c2_.y) + (c3.x + c3.y));

        // step t (even): bitwise identical to sequential version
        const float err0 = kv0 - u0 / (kk0 + 1e-6f);
        float pe0 = err0 * err0;
        #pragma unroll
        for (int o = 16; o; o >>= 1) pe0 += __shfl_xor_sync(0xffffffffu, pe0, o);
        if (lane == 0) red0[wid] = pe0;
        __syncthreads();                                  // BAR-B
        const float ee0 = (red0[0] + red0[1]) + (red0[2] + red0[3]);
        const bool gate0 = ee0 > 0.16f * kk0;

        // step t+1 via rank-1 correction
        const float vp1 = gate0 ? fmaf(err0, kd01, u1) : u1;
        const float err1 = kv1 - vp1 / (kk1 + 1e-6f);
        float pe1 = err1 * err1;
        #pragma unroll
        for (int o = 16; o; o >>= 1) pe1 += __shfl_xor_sync(0xffffffffu, pe1, o);
        if (lane == 0) red1[wid] = pe1;
        __syncthreads();                                  // BAR-C
        const float ee1 = (red1[0] + red1[1]) + (red1[2] + red1[3]);
        const bool gate1 = ee1 > 0.16f * kk1;

        // fused updates, sequential rounding order preserved
        if (gate0 && gate1) {
            const float2 e0 = make_float2(err0, err0);
            const float2 e1 = make_float2(err1, err1);
            #pragma unroll
            for (int q = 0; q < 32; q++) {
                float4 kq0 = k40[q];
                float4 kq1 = k41[q];
                const float2* kp0 = reinterpret_cast<const float2*>(&kq0);
                const float2* kp1 = reinterpret_cast<const float2*>(&kq1);
                Mr[2 * q + 0] = ffma2(e1, kp1[0], ffma2(e0, kp0[0], Mr[2 * q + 0]));
                Mr[2 * q + 1] = ffma2(e1, kp1[1], ffma2(e0, kp0[1], Mr[2 * q + 1]));
            }
        } else if (gate0) {
            const float2 e0 = make_float2(err0, err0);
            #pragma unroll
            for (int q = 0; q < 32; q++) {
                float4 kq0 = k40[q];
                const float2* kp0 = reinterpret_cast<const float2*>(&kq0);
                Mr[2 * q + 0] = ffma2(e0, kp0[0], Mr[2 * q + 0]);
                Mr[2 * q + 1] = ffma2(e0, kp0[1], Mr[2 * q + 1]);
            }
        } else if (gate1) {
            const float2 e1 = make_float2(err1, err1);
            #pragma unroll
            for (int q = 0; q < 32; q++) {
                float4 kq1 = k41[q];
                const float2* kp1 = reinterpret_cast<const float2*>(&kq1);
                Mr[2 * q + 0] = ffma2(e1, kp1[0], Mr[2 * q + 0]);
                Mr[2 * q + 1] = ffma2(e1, kp1[1], Mr[2 * q + 1]);
            }
        }

        kv0 = kvn0; kv1 = kvn1;
        kk0 = kkn0; kk1 = kkn1; kd01 = kdn;
    }

    // leftover single step t = 2046 (kv0 = h[2046], kk0 = kk[2046])
    {
        ks[0][0][tid] = kv0;
        __syncthreads();
        const float4* k4 = (const float4*)ks[0][0];
        float2 a0 = make_float2(0.f, 0.f), a1 = a0, a2 = a0, a3 = a0;
        #pragma unroll
        for (int q = 0; q < 32; q += 2) {
            float4 ka = k4[q];
            float4 kb = k4[q + 1];
            const float2* kap = reinterpret_cast<const float2*>(&ka);
            const float2* kbp = reinterpret_cast<const float2*>(&kb);
            a0 = ffma2(Mr[2 * q + 0], kap[0], a0);
            a1 = ffma2(Mr[2 * q + 1], kap[1], a1);
            a2 = ffma2(Mr[2 * q + 2], kbp[0], a2);
            a3 = ffma2(Mr[2 * q + 3], kbp[1], a3);
        }
        const float u0 = ((a0.x + a0.y) + (a1.x + a1.y))
                       + ((a2.x + a2.y) + (a3.x + a3.y));
        const float err = kv0 - u0 / (kk0 + 1e-6f);
        float pe = err * err;
        #pragma unroll
        for (int o = 16; o; o >>= 1) pe += __shfl_xor_sync(0xffffffffu, pe, o);
        if (lane == 0) red0[wid] = pe;
        __syncthreads();
        const float ee = (red0[0] + red0[1]) + (red0[2] + red0[3]);
        if (ee > 0.16f * kk0) {
            const float2 e2 = make_float2(err, err);
            #pragma unroll
            for (int q = 0; q < 32; q++) {
                float4 kq = k4[q];
                const float2* kp = reinterpret_cast<const float2*>(&kq);
                Mr[2 * q + 0] = ffma2(e2, kp[0], Mr[2 * q + 0]);
                Mr[2 * q + 1] = ffma2(e2, kp[1], Mr[2 * q + 1]);
            }
        }
    }

    // epilogue: r = M . h_last (kv1 holds h[2047])
    ks[0][1][tid] = kv1;
    __syncthreads();
    const float4* k4 = (const float4*)ks[0][1];
    float2 a0 = make_float2(0.f, 0.f), a1 = a0, a2 = a0, a3 = a0;
    #pragma unroll
    for (int q = 0; q < 32; q += 2) {
        float4 ka = k4[q];
        float4 kb = k4[q + 1];
        const float2* kap = reinterpret_cast<const float2*>(&ka);
        const float2* kbp = reinterpret_cast<const float2*>(&kb);
        a0 = ffma2(Mr[2 * q + 0], kap[0], a0);
        a1 = ffma2(Mr[2 * q + 1], kap[1], a1);
        a2 = ffma2(Mr[2 * q + 2], kbp[0], a2);
        a3 = ffma2(Mr[2 * q + 3], kbp[1], a3);
    }
    g_r[b * H + tid] = ((a0.x + a0.y) + (a1.x + a1.y))
                     + ((a2.x + a2.y) + (a3.x + a3.y));
}

// ---------------------------------------------------------------------------
__global__ void rp_kernel(const float* __restrict__ Wrp, const float* __restrict__ brp)
{
    const int b = blockIdx.x;
    const int i = threadIdx.x;
    __shared__ float rb[H];
    rb[i] = g_r[b * H + i];
    __syncthreads();
    float acc = brp[i];
    #pragma unroll 8
    for (int j = 0; j < H; j++) acc += rb[j] * Wrp[j * H + i];
    g_rp[b * H + i] = acc;
}

// ---------------------------------------------------------------------------
__global__ void __launch_bounds__(256) out_kernel(
    const float* __restrict__ Wout, const float* __restrict__ bout,
    float* __restrict__ out)
{
    __shared__ float rp_sm[64 * H];
    const int t = threadIdx.x;
    const int v0 = blockIdx.x * 128;
    const int b0 = blockIdx.y * 64;

    #pragma unroll
    for (int i = 0; i < 32; i++) {
        int idx = i * 256 + t;
        rp_sm[idx] = g_rp[b0 * H + idx];
    }
    __syncthreads();

    const int tx = t & 31;
    const int ty = t >> 5;
    const int m0 = ty * 8;
    const int n  = v0 + tx * 4;

    float2 acc[8][2];
    #pragma unroll
    for (int i = 0; i < 8; i++) {
        acc[i][0] = make_float2(0.f, 0.f);
        acc[i][1] = make_float2(0.f, 0.f);
    }

    #pragma unroll 2
    for (int k = 0; k < H; k++) {
        float4 wv = *(const float4*)(Wout + (size_t)k * V + n);
        const float2* wp = reinterpret_cast<const float2*>(&wv);
        #pragma unroll
        for (int i = 0; i < 8; i++) {
            float hv = rp_sm[(m0 + i) * H + k];
            float2 h2 = make_float2(hv, hv);
            acc[i][0] = ffma2(h2, wp[0], acc[i][0]);
            acc[i][1] = ffma2(h2, wp[1], acc[i][1]);
        }
    }
    const float4 bo = *(const float4*)(bout + n);
    #pragma unroll
    for (int i = 0; i < 8; i++) {
        float4 o;
        o.x = acc[i][0].x + bo.x; o.y = acc[i][0].y + bo.y;
        o.z = acc[i][1].x + bo.z; o.w = acc[i][1].y + bo.w;
        *(float4*)(out + (size_t)(b0 + m0 + i) * V + n) = o;
    }
}

// ---------------------------------------------------------------------------
extern "C" void kernel_launch(void* const* d_in, const int* in_sizes, int n_in,
                              void* d_out, int out_size)
{
    const int*   seq   = (const int*)  d_in[0];
    const float* embed = (const float*)d_in[1];
    const float* W1    = (const float*)d_in[2];
    const float* b1    = (const float*)d_in[3];
    const float* W2    = (const float*)d_in[4];
    const float* b2    = (const float*)d_in[5];
    const float* gamma = (const float*)d_in[6];
    const float* beta  = (const float*)d_in[7];
    const float* Wrp   = (const float*)d_in[8];
    const float* brp   = (const float*)d_in[9];
    const float* Wout  = (const float*)d_in[10];
    const float* bout  = (const float*)d_in[11];
    float* out = (float*)d_out;

    cudaFuncSetAttribute(encode_mma_kernel,
                         cudaFuncAttributeMaxDynamicSharedMemorySize, ENC_SMEM);

    prep_kernel<<<256, 256>>>(W1, W2);
    encode_mma_kernel<<<BL / TOK, 256, ENC_SMEM>>>(seq, embed, b1, b2, gamma, beta);
    dim3 ng(B, 16);
    norms_kernel<<<ng, 128>>>();
    scan_kernel<<<B, 128>>>();
    rp_kernel<<<B, H>>>(Wrp, brp);
    dim3 og(V / 128, B / 64);
    out_kernel<<<og, 256>>>(Wout, bout, out);
}

// round 13
// speedup vs baseline: 1.0355x; 1.0054x over previous
#include <cuda_runtime.h>
#include <cuda_bf16.h>
#include <cstdint>
#include <cstddef>

#define B 256
#define L 2048
#define H 128
#define V 32000
#define BL (B * L)
#define TOK 128

typedef unsigned long long u64;
typedef uint32_t u32;

// ---------------------------------------------------------------------------
// helpers
// ---------------------------------------------------------------------------
__device__ __forceinline__ u32 smem_u32(const void* p) {
    return (u32)__cvta_generic_to_shared(p);
}

__device__ __forceinline__ void ldsm_x4(u32* r, u32 addr) {
    asm volatile("ldmatrix.sync.aligned.m8n8.x4.shared.b16 {%0,%1,%2,%3}, [%4];"
                 : "=r"(r[0]), "=r"(r[1]), "=r"(r[2]), "=r"(r[3]) : "r"(addr));
}

__device__ __forceinline__ void mma16816(float* d, const u32* a, u32 b0, u32 b1) {
    asm volatile(
        "mma.sync.aligned.m16n8k16.row.col.f32.bf16.bf16.f32 "
        "{%0,%1,%2,%3}, {%4,%5,%6,%7}, {%8,%9}, {%0,%1,%2,%3};"
        : "+f"(d[0]), "+f"(d[1]), "+f"(d[2]), "+f"(d[3])
        : "r"(a[0]), "r"(a[1]), "r"(a[2]), "r"(a[3]), "r"(b0), "r"(b1));
}

__device__ __forceinline__ void cp16(u32 dst, const void* src) {
    asm volatile("cp.async.cg.shared.global [%0], [%1], 16;" :: "r"(dst), "l"(src));
}

// Packed dual-FMA (scan/out kernels).
__device__ __forceinline__ float2 ffma2(float2 a, float2 b, float2 c) {
    float2 d;
    asm("fma.rn.f32x2 %0, %1, %2, %3;"
        : "=l"(*(u64*)&d)
        : "l"(*(u64*)&a), "l"(*(u64*)&b), "l"(*(u64*)&c));
    return d;
}

// 3-way bf16 split: x = a0+a1+a2 + O(2^-27 * x)
__device__ __forceinline__ void split3(float x, __nv_bfloat16* a) {
    a[0] = __float2bfloat16(x);
    float r = x - __bfloat162float(a[0]);
    a[1] = __float2bfloat16(r);  r -= __bfloat162float(a[1]);
    a[2] = __float2bfloat16(r);
}
__device__ __forceinline__ u32 pack_bf2(__nv_bfloat16 lo, __nv_bfloat16 hi) {
    __nv_bfloat162 p;
    p.x = lo; p.y = hi;
    return *(u32*)&p;
}

// XOR chunk swizzles: conflict-free ldmatrix on natural row strides.
__device__ __forceinline__ u32 swz256(int row, int kb) {
    return (u32)(row * 256 + ((((kb >> 4) ^ (row & 7)) << 4) | (kb & 15)));
}
__device__ __forceinline__ u32 swz128(int row, int kb) {
    return (u32)(row * 128 + ((((kb >> 4) ^ (row & 7)) << 4) | (kb & 15)));
}

// ---------------------------------------------------------------------------
// Scratch device globals.
// ---------------------------------------------------------------------------
__device__ float g_h[(size_t)BL * H];
__device__ float g_rp[B * H];
// Pre-split, pre-swizzled weight part-tiles (3 parts):
// g_W1s: [c=4][p=3][16384]  tile = 64 n-rows x 128 k bf16, swz256 rows
// g_W2s: [c=4][p=3][16384]  tile = 128 n-rows x 64 k bf16, swz128 rows
__device__ unsigned char g_W1s[4 * 3 * 16384];
__device__ unsigned char g_W2s[4 * 3 * 16384];

// ---------------------------------------------------------------------------
// Prep: split3 + transpose + swizzle the weights.
// ---------------------------------------------------------------------------
__global__ void __launch_bounds__(256) prep_kernel(
    const float* __restrict__ W1, const float* __restrict__ W2)
{
    int idx = blockIdx.x * 256 + threadIdx.x;   // 65536 total
    __nv_bfloat16 pp[3];
    if (idx < H * 2 * H) {                      // W1: [k=128][n=256]
        int k = idx >> 8;
        int n = idx & 255;
        split3(W1[idx], pp);
        int c = n >> 6, nl = n & 63;
        u32 off = swz256(nl, 2 * k);
        unsigned char* base = g_W1s + (size_t)c * 49152 + off;
        #pragma unroll
        for (int p = 0; p < 3; p++)
            *(__nv_bfloat16*)(base + p * 16384) = pp[p];
    } else {                                    // W2: [k2=256][n=128]
        int j  = idx - H * 2 * H;
        int k2 = j >> 7;
        int n  = j & 127;
        split3(W2[j], pp);
        int c = k2 >> 6, kl = k2 & 63;
        u32 off = swz128(n, 2 * kl);
        unsigned char* base = g_W2s + (size_t)c * 49152 + off;
        #pragma unroll
        for (int p = 0; p < 3; p++)
            *(__nv_bfloat16*)(base + p * 16384) = pp[p];
    }
}

// Stage schedule: s = c*6 + g*3 + jj, W part j = 2-jj (smallest products first).
__device__ __forceinline__ const unsigned char* stage_src(int s) {
    int c = s / 6, g = (s / 3) % 2, jj = s % 3;
    int j = 2 - jj;
    return (g ? g_W2s : g_W1s) + (size_t)c * 49152 + (size_t)j * 16384;
}

// ---------------------------------------------------------------------------
// Encode: R10 configuration (256 threads, triple-buffered W, pipelined ldsm).
// Math order: W parts j=2,1,0; A parts i descending; k16 descending — the
// proven bitwise configuration (rel_err 1.060308e-06).
// SMEM (199168 B): E 3x32768 @0 | A2 3x16384 @98304 | W 3x16384 @147456
// ---------------------------------------------------------------------------
#define EO       0
#define EPART    32768
#define A2O      98304
#define A2PART   16384
#define WO       147456
#define CO       196608
#define ENC_SMEM 199168

__global__ void __launch_bounds__(256, 1) encode_mma_kernel(
    const int* __restrict__ seq, const float* __restrict__ embed,
    const float* __restrict__ b1, const float* __restrict__ b2,
    const float* __restrict__ gamma, const float* __restrict__ beta)
{
    extern __shared__ char smc[];
    const u32 sb = smem_u32(smc);
    float* b1s = (float*)(smc + CO);
    float* b2s = b1s + 256;
    float* gs  = b2s + 128;
    float* bs  = gs + 128;

    const int t    = threadIdx.x;
    const int lane = t & 31;
    const int w    = t >> 5;
    const int tile0 = blockIdx.x * TOK;

    {
        const unsigned char* src = stage_src(0) + t * 64;
        u32 dst = sb + WO + t * 64;
        cp16(dst, src); cp16(dst + 16, src + 16);
        cp16(dst + 32, src + 32); cp16(dst + 48, src + 48);
        asm volatile("cp.async.commit_group;");
    }

    b1s[t] = b1[t];
    if (t < 128) { b2s[t] = b2[t]; gs[t] = gamma[t]; bs[t] = beta[t]; }

    {
        int row = t >> 1, kh = t & 1;
        int tok = seq[tile0 + row];
        const float4* er = (const float4*)(embed + (size_t)tok * H) + kh * 16;
        #pragma unroll 4
        for (int i = 0; i < 16; i++) {
            float4 v = er[i];
            int col0 = kh * 64 + 4 * i;
            u32 offA = swz256(row, 2 * col0);
            __nv_bfloat16 px[3], py[3];
            split3(v.x, px); split3(v.y, py);
            #pragma unroll
            for (int p = 0; p < 3; p++)
                *(u32*)(smc + EO + p * EPART + offA) = pack_bf2(px[p], py[p]);
            split3(v.z, px); split3(v.w, py);
            #pragma unroll
            for (int p = 0; p < 3; p++)
                *(u32*)(smc + EO + p * EPART + offA + 4) = pack_bf2(px[p], py[p]);
        }
    }

    const int m0   = (w >> 1) * 32;
    const int n0g1 = (w & 1) * 32;
    const int n0g2 = (w & 1) * 64;
    const int lg   = lane >> 3;
    const int rsel = (lane & 7) + ((lg & 1) << 3);
    const int kbs  = (lg >> 1) << 4;
    const int frow = lane >> 2;
    const int fcol = 2 * (lane & 3);

    float c1[2][4][4];
    float c2[2][8][4];
    #pragma unroll
    for (int mt = 0; mt < 2; mt++)
        #pragma unroll
        for (int nt = 0; nt < 8; nt++)
            #pragma unroll
            for (int jj = 0; jj < 4; jj++) c2[mt][nt][jj] = 0.f;

    for (int s = 0; s < 24; s++) {
        const int jj  = s % 3;
        const int j   = 2 - jj;
        const int g   = (s / 3) % 2;
        const int buf = s % 3;

        if (s < 23) {
            const unsigned char* src = stage_src(s + 1) + t * 64;
            u32 dst = sb + WO + ((s + 1) % 3) * 16384 + t * 64;
            cp16(dst, src); cp16(dst + 16, src + 16);
            cp16(dst + 32, src + 32); cp16(dst + 48, src + 48);
            asm volatile("cp.async.commit_group;");
            asm volatile("cp.async.wait_group 1;");
        } else {
            asm volatile("cp.async.wait_group 0;");
        }
        __syncthreads();

        const u32 Bb = sb + WO + buf * 16384;

        if (g == 0) {
            if (jj == 0) {
                #pragma unroll
                for (int mt = 0; mt < 2; mt++)
                    #pragma unroll
                    for (int nt = 0; nt < 4; nt++)
                        #pragma unroll
                        for (int q = 0; q < 4; q++) c1[mt][nt][q] = 0.f;
            }
            for (int i = 2 - j; i >= 0; i--) {
                const u32 Ab = sb + EO + i * EPART;
                u32 af[2][2][4], qf[2][2][4];
                {
                    const int kb = 7 * 32 + kbs;
                    ldsm_x4(af[0][0], Ab + swz256(m0 + rsel, kb));
                    ldsm_x4(af[0][1], Ab + swz256(m0 + 16 + rsel, kb));
                    ldsm_x4(qf[0][0], Bb + swz256(n0g1 + rsel, kb));
                    ldsm_x4(qf[0][1], Bb + swz256(n0g1 + 16 + rsel, kb));
                }
                #pragma unroll
                for (int k16 = 7; k16 >= 0; k16--) {
                    const int cur = (7 - k16) & 1;
                    if (k16 > 0) {
                        const int kb2 = (k16 - 1) * 32 + kbs;
                        ldsm_x4(af[cur ^ 1][0], Ab + swz256(m0 + rsel, kb2));
                        ldsm_x4(af[cur ^ 1][1], Ab + swz256(m0 + 16 + rsel, kb2));
                        ldsm_x4(qf[cur ^ 1][0], Bb + swz256(n0g1 + rsel, kb2));
                        ldsm_x4(qf[cur ^ 1][1], Bb + swz256(n0g1 + 16 + rsel, kb2));
                    }
                    #pragma unroll
                    for (int mt = 0; mt < 2; mt++)
                        #pragma unroll
                        for (int nt = 0; nt < 4; nt++)
                            mma16816(c1[mt][nt], af[cur][mt],
                                     qf[cur][nt >> 1][nt & 1],
                                     qf[cur][nt >> 1][2 + (nt & 1)]);
                }
            }
            if (jj == 2) {
                const int c = s / 6;
                #pragma unroll
                for (int mt = 0; mt < 2; mt++) {
                    #pragma unroll
                    for (int nt = 0; nt < 4; nt++) {
                        int col = n0g1 + nt * 8 + fcol;
                        float bb0 = b1s[c * 64 + col];
                        float bb1 = b1s[c * 64 + col + 1];
                        #pragma unroll
                        for (int half = 0; half < 2; half++) {
                            int row = m0 + mt * 16 + frow + half * 8;
                            float h0 = fmaxf(c1[mt][nt][2 * half + 0] + bb0, 0.f);
                            float h1 = fmaxf(c1[mt][nt][2 * half + 1] + bb1, 0.f);
                            __nv_bfloat16 px[3], py[3];
                            split3(h0, px); split3(h1, py);
                            u32 off = swz128(row, 2 * col);
                            #pragma unroll
                            for (int p = 0; p < 3; p++)
                                *(u32*)(smc + A2O + p * A2PART + off) =
                                    pack_bf2(px[p], py[p]);
                        }
                    }
                }
            }
        } else {
            for (int i = 2 - j; i >= 0; i--) {
                const u32 Ab = sb + A2O + i * A2PART;
                u32 af[2][2][4], qf[2][4][4];
                {
                    const int kb = 3 * 32 + kbs;
                    ldsm_x4(af[0][0], Ab + swz128(m0 + rsel, kb));
                    ldsm_x4(af[0][1], Ab + swz128(m0 + 16 + rsel, kb));
                    #pragma unroll
                    for (int nt2 = 0; nt2 < 4; nt2++)
                        ldsm_x4(qf[0][nt2], Bb + swz128(n0g2 + nt2 * 16 + rsel, kb));
                }
                #pragma unroll
                for (int k16 = 3; k16 >= 0; k16--) {
                    const int cur = (3 - k16) & 1;
                    if (k16 > 0) {
                        const int kb2 = (k16 - 1) * 32 + kbs;
                        ldsm_x4(af[cur ^ 1][0], Ab + swz128(m0 + rsel, kb2));
                        ldsm_x4(af[cur ^ 1][1], Ab + swz128(m0 + 16 + rsel, kb2));
                        #pragma unroll
                        for (int nt2 = 0; nt2 < 4; nt2++)
                            ldsm_x4(qf[cur ^ 1][nt2],
                                    Bb + swz128(n0g2 + nt2 * 16 + rsel, kb2));
                    }
                    #pragma unroll
                    for (int mt = 0; mt < 2; mt++)
                        #pragma unroll
                        for (int nt = 0; nt < 8; nt++)
                            mma16816(c2[mt][nt], af[cur][mt],
                                     qf[cur][nt >> 1][nt & 1],
                                     qf[cur][nt >> 1][2 + (nt & 1)]);
                }
            }
        }
    }

    #pragma unroll
    for (int mt = 0; mt < 2; mt++) {
        #pragma unroll
        for (int nt = 0; nt < 8; nt++) {
            int col = n0g2 + nt * 8 + fcol;
            float bb0 = b2s[col], bb1 = b2s[col + 1];
            #pragma unroll
            for (int half = 0; half < 2; half++) {
                int row = m0 + mt * 16 + frow + half * 8;
                u32 off = swz256(row, 2 * col);
                float e0 = 0.f, e1 = 0.f;
                #pragma unroll
                for (int p = 2; p >= 0; p--) {
                    u32 ev = *(u32*)(smc + EO + p * EPART + off);
                    __nv_bfloat162 eb = *(__nv_bfloat162*)&ev;
                    e0 += __bfloat162float(eb.x);
                    e1 += __bfloat162float(eb.y);
                }
                c2[mt][nt][2 * half + 0] += bb0 + e0;
                c2[mt][nt][2 * half + 1] += bb1 + e1;
            }
        }
    }
    __syncthreads();

    float* ySM = (float*)(smc + EO);
    float* muS = (float*)(smc + A2O);
    float* ivS = muS + 128;
    #pragma unroll
    for (int mt = 0; mt < 2; mt++) {
        #pragma unroll
        for (int nt = 0; nt < 8; nt++) {
            int col = n0g2 + nt * 8 + fcol;
            #pragma unroll
            for (int half = 0; half < 2; half++) {
                int row = m0 + mt * 16 + frow + half * 8;
                *(float2*)(ySM + row * 132 + col) =
                    make_float2(c2[mt][nt][2 * half + 0], c2[mt][nt][2 * half + 1]);
            }
        }
    }
    __syncthreads();

    if (t < 128) {
        const float4* yr = (const float4*)(ySM + t * 132);
        float s = 0.f, q = 0.f;
        #pragma unroll 8
        for (int jj = 0; jj < 32; jj++) {
            float4 y = yr[jj];
            s += (y.x + y.y) + (y.z + y.w);
            q += y.x * y.x + y.y * y.y + y.z * y.z + y.w * y.w;
        }
        float mu  = s * (1.0f / H);
        float var = q * (1.0f / H) - mu * mu;
        muS[t] = mu;
        ivS[t] = rsqrtf(var + 1e-5f);
    }
    __syncthreads();

    #pragma unroll
    for (int i = t; i < 128 * 32; i += 256) {
        int row = i >> 5, jj = i & 31;
        float4 y = ((const float4*)(ySM + row * 132))[jj];
        float mu = muS[row], iv = ivS[row];
        float4 g4 = ((const float4*)gs)[jj];
        float4 b4 = ((const float4*)bs)[jj];
        float4 o4;
        o4.x = (y.x - mu) * iv * g4.x + b4.x;
        o4.y = (y.y - mu) * iv * g4.y + b4.y;
        o4.z = (y.z - mu) * iv * g4.z + b4.z;
        o4.w = (y.w - mu) * iv * g4.w + b4.w;
        ((float4*)(g_h + (size_t)(tile0 + row) * H))[jj] = o4;
    }
}

// ---------------------------------------------------------------------------
// Scan (R10 bitwise-proven version) + fused rp epilogue.
// One CTA per batch, 128 threads, inline kk/ee reductions.
// ---------------------------------------------------------------------------
__global__ void __launch_bounds__(128, 2) scan_kernel(
    const float* __restrict__ Wrp, const float* __restrict__ brp)
{
    const int b = blockIdx.x;
    const int tid = threadIdx.x;
    const int lane = tid & 31;
    const int wid = tid >> 5;

    __shared__ float ks[2][H];
    __shared__ float red_kk[4];
    __shared__ float red_ee[4];

    float2 Mr[64];
    #pragma unroll
    for (int q = 0; q < 64; q++) Mr[q] = make_float2(0.f, 0.f);

    const float* hb = g_h + (size_t)b * L * H;
    float kv_next = hb[tid];

    for (int t = 0; t < L - 1; t++) {
        const int buf = t & 1;
        const float kv = kv_next;
        ks[buf][tid] = kv;

        float p = kv * kv;
        #pragma unroll
        for (int o = 16; o; o >>= 1) p += __shfl_xor_sync(0xffffffffu, p, o);
        if (lane == 0) red_kk[wid] = p;
        __syncthreads();

        kv_next = hb[(size_t)(t + 1) * H + tid];
        const float kk = (red_kk[0] + red_kk[1]) + (red_kk[2] + red_kk[3]);

        const float4* k4 = (const float4*)ks[buf];
        float2 a0 = make_float2(0.f, 0.f), a1 = a0, a2 = a0, a3 = a0;
        #pragma unroll
        for (int q = 0; q < 32; q += 2) {
            float4 ka = k4[q];
            float4 kb = k4[q + 1];
            const float2* kap = reinterpret_cast<const float2*>(&ka);
            const float2* kbp = reinterpret_cast<const float2*>(&kb);
            a0 = ffma2(Mr[2 * q + 0], kap[0], a0);
            a1 = ffma2(Mr[2 * q + 1], kap[1], a1);
            a2 = ffma2(Mr[2 * q + 2], kbp[0], a2);
            a3 = ffma2(Mr[2 * q + 3], kbp[1], a3);
        }
        const float vp = ((a0.x + a0.y) + (a1.x + a1.y))
                       + ((a2.x + a2.y) + (a3.x + a3.y));
        const float err = kv - vp / (kk + 1e-6f);

        float pe = err * err;
        #pragma unroll
        for (int o = 16; o; o >>= 1) pe += __shfl_xor_sync(0xffffffffu, pe, o);
        if (lane == 0) red_ee[wid] = pe;
        __syncthreads();
        const float ee = (red_ee[0] + red_ee[1]) + (red_ee[2] + red_ee[3]);

        if (ee > 0.16f * kk) {
            const float2 e2 = make_float2(err, err);
            #pragma unroll
            for (int q = 0; q < 32; q++) {
                float4 kq = k4[q];
                const float2* kp = reinterpret_cast<const float2*>(&kq);
                Mr[2 * q + 0] = ffma2(e2, kp[0], Mr[2 * q + 0]);
                Mr[2 * q + 1] = ffma2(e2, kp[1], Mr[2 * q + 1]);
            }
        }
    }

    ks[1][tid] = kv_next;
    __syncthreads();
    const float4* k4 = (const float4*)ks[1];
    float2 a0 = make_float2(0.f, 0.f), a1 = a0, a2 = a0, a3 = a0;
    #pragma unroll
    for (int q = 0; q < 32; q += 2) {
        float4 ka = k4[q];
        float4 kb = k4[q + 1];
        const float2* kap = reinterpret_cast<const float2*>(&ka);
        const float2* kbp = reinterpret_cast<const float2*>(&kb);
        a0 = ffma2(Mr[2 * q + 0], kap[0], a0);
        a1 = ffma2(Mr[2 * q + 1], kap[1], a1);
        a2 = ffma2(Mr[2 * q + 2], kbp[0], a2);
        a3 = ffma2(Mr[2 * q + 3], kbp[1], a3);
    }
    const float rv = ((a0.x + a0.y) + (a1.x + a1.y))
                   + ((a2.x + a2.y) + (a3.x + a3.y));

    // ---- fused rp = r @ Wrp + brp (output-head only; no gate impact) ----
    __syncthreads();              // all update-loop reads of ks done
    ks[0][tid] = rv;
    __syncthreads();
    float acc = brp[tid];
    #pragma unroll 8
    for (int j = 0; j < H; j++) acc += ks[0][j] * Wrp[j * H + tid];
    g_rp[b * H + tid] = acc;
}

// ---------------------------------------------------------------------------
__global__ void __launch_bounds__(256) out_kernel(
    const float* __restrict__ Wout, const float* __restrict__ bout,
    float* __restrict__ out)
{
    __shared__ float rp_sm[64 * H];
    const int t = threadIdx.x;
    const int v0 = blockIdx.x * 128;
    const int b0 = blockIdx.y * 64;

    #pragma unroll
    for (int i = 0; i < 32; i++) {
        int idx = i * 256 + t;
        rp_sm[idx] = g_rp[b0 * H + idx];
    }
    __syncthreads();

    const int tx = t & 31;
    const int ty = t >> 5;
    const int m0 = ty * 8;
    const int n  = v0 + tx * 4;

    float2 acc[8][2];
    #pragma unroll
    for (int i = 0; i < 8; i++) {
        acc[i][0] = make_float2(0.f, 0.f);
        acc[i][1] = make_float2(0.f, 0.f);
    }

    #pragma unroll 2
    for (int k = 0; k < H; k++) {
        float4 wv = *(const float4*)(Wout + (size_t)k * V + n);
        const float2* wp = reinterpret_cast<const float2*>(&wv);
        #pragma unroll
        for (int i = 0; i < 8; i++) {
            float hv = rp_sm[(m0 + i) * H + k];
            float2 h2 = make_float2(hv, hv);
            acc[i][0] = ffma2(h2, wp[0], acc[i][0]);
            acc[i][1] = ffma2(h2, wp[1], acc[i][1]);
        }
    }
    const float4 bo = *(const float4*)(bout + n);
    #pragma unroll
    for (int i = 0; i < 8; i++) {
        float4 o;
        o.x = acc[i][0].x + bo.x; o.y = acc[i][0].y + bo.y;
        o.z = acc[i][1].x + bo.z; o.w = acc[i][1].y + bo.w;
        *(float4*)(out + (size_t)(b0 + m0 + i) * V + n) = o;
    }
}

// ---------------------------------------------------------------------------
extern "C" void kernel_launch(void* const* d_in, const int* in_sizes, int n_in,
                              void* d_out, int out_size)
{
    const int*   seq   = (const int*)  d_in[0];
    const float* embed = (const float*)d_in[1];
    const float* W1    = (const float*)d_in[2];
    const float* b1    = (const float*)d_in[3];
    const float* W2    = (const float*)d_in[4];
    const float* b2    = (const float*)d_in[5];
    const float* gamma = (const float*)d_in[6];
    const float* beta  = (const float*)d_in[7];
    const float* Wrp   = (const float*)d_in[8];
    const float* brp   = (const float*)d_in[9];
    const float* Wout  = (const float*)d_in[10];
    const float* bout  = (const float*)d_in[11];
    float* out = (float*)d_out;

    cudaFuncSetAttribute(encode_mma_kernel,
                         cudaFuncAttributeMaxDynamicSharedMemorySize, ENC_SMEM);

    // 4 launches/call, encode at position 2 -> ncu (-s 5 -c 1) captures encode.
    prep_kernel<<<256, 256>>>(W1, W2);
    encode_mma_kernel<<<BL / TOK, 256, ENC_SMEM>>>(seq, embed, b1, b2, gamma, beta);
    scan_kernel<<<B, 128>>>(Wrp, brp);
    dim3 og(V / 128, B / 64);
    out_kernel<<<og, 256>>>(Wout, bout, out);
}